// round 2
// baseline (speedup 1.0000x reference)
#include <cuda_runtime.h>

// NeuralNetwork_81003083203462 — 16-layer chained GEMV (2048x2048 fp32) + bias + SiLU.
// Single persistent kernel, grid-wide software barrier between layers.
// Masks are structurally all-ones (W*1 == W bitwise) -> not read, halving HBM traffic.

#define LAYERS 16
#define BDIM   2048
#define NINPUT 2048
#define GRID   148
#define TPB    1024

__device__ float    g_values[NINPUT + LAYERS * BDIM];
__device__ unsigned g_count = 0;
__device__ unsigned g_gen   = 0;

__device__ __forceinline__ void grid_barrier() {
    __syncthreads();
    if (threadIdx.x == 0) {
        __threadfence();
        volatile unsigned* gen_p = &g_gen;
        unsigned gen = *gen_p;                 // snapshot BEFORE arriving
        unsigned old = atomicAdd(&g_count, 1);
        if (old == GRID - 1) {
            atomicExch(&g_count, 0);           // reset for next barrier / next replay
            __threadfence();
            atomicAdd(&g_gen, 1);              // release
        } else {
            while (*gen_p == gen) { __nanosleep(32); }
        }
        __threadfence();
    }
    __syncthreads();
}

__global__ void __launch_bounds__(TPB, 1) mlp_chain_kernel(
    const float* __restrict__ x,
    const float* __restrict__ W,        // [L, B, B] row-major
    const float* __restrict__ biases,   // [L, B]
    const int*   __restrict__ indices,  // [L, B] global ids of predecessors
    const int*   __restrict__ tb,       // [L, B] global ids of this batch
    float*       __restrict__ out)      // [B]
{
    __shared__ float vals[BDIM];
    __shared__ float red[32];

    const int tid  = threadIdx.x;
    const int warp = tid >> 5;
    const int lane = tid & 31;
    const int grp  = warp >> 1;     // 0..15 : row group (2 warps per row)
    const int half = warp & 1;      // which half of the 2048-wide row

    const int row = blockIdx.x + GRID * grp;   // may be >= BDIM (idle group)

    for (int l = 0; l < LAYERS; ++l) {
        // Stage this layer's input vector into shared memory (gather via indices).
        for (int t = tid; t < BDIM; t += TPB) {
            int id = indices[l * BDIM + t];
            vals[t] = (id < NINPUT) ? x[id] : g_values[id];
        }
        __syncthreads();

        // Each 64-thread group computes one output row: dot(W[l][row], vals).
        float acc = 0.f;
        if (row < BDIM) {
            const float4* Wrow = reinterpret_cast<const float4*>(W)
                               + ((size_t)l * BDIM + row) * (BDIM / 4)
                               + half * (BDIM / 8);
            const float4* V = reinterpret_cast<const float4*>(vals) + half * (BDIM / 8);
            #pragma unroll
            for (int k = 0; k < 8; ++k) {
                float4 w = __ldcs(&Wrow[k * 32 + lane]);   // streaming: no reuse
                float4 v = V[k * 32 + lane];
                acc += w.x * v.x + w.y * v.y + w.z * v.z + w.w * v.w;
            }
        }
        #pragma unroll
        for (int o = 16; o > 0; o >>= 1)
            acc += __shfl_down_sync(0xffffffffu, acc, o);
        if (lane == 0) red[warp] = acc;
        __syncthreads();

        // One thread per row-group: combine halves, bias, activation, scatter.
        if (tid < 16) {
            int r = blockIdx.x + GRID * tid;
            if (r < BDIM) {
                float s = red[2 * tid] + red[2 * tid + 1] + biases[l * BDIM + r];
                if (l == LAYERS - 1) {
                    out[r] = s;                                  // output: identity
                } else {
                    float sv = s / (1.f + __expf(-s));           // silu
                    g_values[tb[l * BDIM + r]] = sv;
                }
            }
        }
        if (l < LAYERS - 1) grid_barrier();
    }
}

extern "C" void kernel_launch(void* const* d_in, const int* in_sizes, int n_in,
                              void* d_out, int out_size)
{
    const float* x       = (const float*)d_in[0];
    const float* weights = (const float*)d_in[1];
    // d_in[2] = masks: structurally all-ones, intentionally unused (W*1 == W bitwise)
    const float* biases  = (const float*)d_in[3];
    const int*   indices = (const int*)  d_in[4];
    const int*   tb      = (const int*)  d_in[5];
    float*       out     = (float*)d_out;

    mlp_chain_kernel<<<GRID, TPB>>>(x, weights, biases, indices, tb, out);
}

// round 3
// speedup vs baseline: 1.0392x; 1.0392x over previous
#include <cuda_runtime.h>

// NeuralNetwork_81003083203462 — 16-layer chained GEMV (2048x2048 fp32) + bias + SiLU.
// R2: persistent kernel + grid barrier, PLUS
//   (a) L2 prefetch of layer l+1 weights during layer l  -> DRAM streams continuously
//   (b) weight loads issued into registers BEFORE the activation gather -> gather hidden
// Masks are structurally all-ones (W*1 == W bitwise) -> never read.

#define LAYERS 16
#define BDIM   2048
#define NINPUT 2048
#define GRID   148
#define TPB    1024

__device__ float    g_values[NINPUT + LAYERS * BDIM];
__device__ unsigned g_count = 0;
__device__ unsigned g_gen   = 0;

__device__ __forceinline__ void grid_barrier() {
    __syncthreads();
    if (threadIdx.x == 0) {
        __threadfence();
        volatile unsigned* gen_p = &g_gen;
        unsigned gen = *gen_p;                 // snapshot BEFORE arriving
        unsigned old = atomicAdd(&g_count, 1);
        if (old == GRID - 1) {
            atomicExch(&g_count, 0);           // reset for next barrier / next replay
            __threadfence();
            atomicAdd(&g_gen, 1);              // release
        } else {
            while (*gen_p == gen) { __nanosleep(32); }
        }
        __threadfence();
    }
    __syncthreads();
}

__global__ void __launch_bounds__(TPB, 1) mlp_chain_kernel(
    const float* __restrict__ x,
    const float* __restrict__ W,        // [L, B, B] row-major
    const float* __restrict__ biases,   // [L, B]
    const int*   __restrict__ indices,  // [L, B] global ids of predecessors
    const int*   __restrict__ tb,       // [L, B] global ids of this batch
    float*       __restrict__ out)      // [B]
{
    __shared__ float vals[BDIM];
    __shared__ float red[32];

    const int tid  = threadIdx.x;
    const int warp = tid >> 5;
    const int lane = tid & 31;
    const int grp  = warp >> 1;     // 0..15 : row group (2 warps per row)
    const int half = warp & 1;      // which half of the 2048-wide row

    const int row = blockIdx.x + GRID * grp;   // may be >= BDIM (idle group)

    for (int l = 0; l < LAYERS; ++l) {
        // ---- 1. Issue this layer's weight loads into registers (L2 hits after
        //         the previous iteration's prefetch), and prefetch next layer. ----
        float4 w[8];
        const float4* Wrow = reinterpret_cast<const float4*>(W)
                           + ((size_t)l * BDIM + row) * (BDIM / 4)
                           + half * (BDIM / 8);
        if (row < BDIM) {
            #pragma unroll
            for (int k = 0; k < 8; ++k)
                w[k] = __ldcs(&Wrow[k * 32 + lane]);
            if (l < LAYERS - 1) {
                const float4* Wnext = Wrow + (size_t)BDIM * (BDIM / 4);
                #pragma unroll
                for (int k = 0; k < 8; ++k)
                    asm volatile("prefetch.global.L2 [%0];"
                                 :: "l"(Wnext + k * 32 + lane));
            }
        }

        // ---- 2. Gather this layer's input vector into shared memory
        //         (overlaps with the weight-load latency above). ----
        for (int t = tid; t < BDIM; t += TPB) {
            int id = indices[l * BDIM + t];
            vals[t] = (id < NINPUT) ? x[id] : g_values[id];
        }
        __syncthreads();

        // ---- 3. Dot product: each 64-thread group owns one output row. ----
        float acc = 0.f;
        if (row < BDIM) {
            const float4* V = reinterpret_cast<const float4*>(vals) + half * (BDIM / 8);
            #pragma unroll
            for (int k = 0; k < 8; ++k) {
                float4 v = V[k * 32 + lane];
                acc += w[k].x * v.x + w[k].y * v.y + w[k].z * v.z + w[k].w * v.w;
            }
        }
        #pragma unroll
        for (int o = 16; o > 0; o >>= 1)
            acc += __shfl_down_sync(0xffffffffu, acc, o);
        if (lane == 0) red[warp] = acc;
        __syncthreads();

        // ---- 4. Combine halves, bias, activation, scatter. ----
        if (tid < 16) {
            int r = blockIdx.x + GRID * tid;
            if (r < BDIM) {
                float s = red[2 * tid] + red[2 * tid + 1] + biases[l * BDIM + r];
                if (l == LAYERS - 1) {
                    out[r] = s;                                  // output: identity
                } else {
                    float sv = s / (1.f + __expf(-s));           // silu
                    g_values[tb[l * BDIM + r]] = sv;
                }
            }
        }
        if (l < LAYERS - 1) grid_barrier();
    }
}

extern "C" void kernel_launch(void* const* d_in, const int* in_sizes, int n_in,
                              void* d_out, int out_size)
{
    const float* x       = (const float*)d_in[0];
    const float* weights = (const float*)d_in[1];
    // d_in[2] = masks: structurally all-ones, intentionally unused (W*1 == W bitwise)
    const float* biases  = (const float*)d_in[3];
    const int*   indices = (const int*)  d_in[4];
    const int*   tb      = (const int*)  d_in[5];
    float*       out     = (float*)d_out;

    mlp_chain_kernel<<<GRID, TPB>>>(x, weights, biases, indices, tb, out);
}